// round 4
// baseline (speedup 1.0000x reference)
#include <cuda_runtime.h>
#include <math.h>

#define N_TOK   49
#define DIM     128
#define NHEADS  4
#define HD      32
#define NWIN    64
#define THREADS 384

// smem layout (float offsets):
#define X_OFF    0        // 6272 floats: x tile 49x128
#define Q_OFF    6272     // 6272: q [h][n][d] (pre-scaled)
#define KT_OFF   12544    // 6272: kT [h][d][n]
#define V_OFF    18816    // 6272: v [h][n][d]
#define MASK_OFF 25088    // 2401: mask window
#define REL_OFF  27489    // 676:  rel_table (169x4)
#define RIDX_B   ((27489 + 676) * 4)   // byte offset of 2401 uint8 rel indices
#define SMEM_BYTES (RIDX_B + 2401 + 11)  // pad a touch

// packed f32x2 FMA: acc.{lo,hi} += a.{lo,hi} * b.{lo,hi}
#define FFMA2(acc, a, b) \
    asm("fma.rn.f32x2 %0, %1, %2, %0;" : "+l"(acc) : "l"(a), "l"(b))

__device__ __forceinline__ float hsum2(unsigned long long p) {
    float lo, hi;
    asm("mov.b64 {%0, %1}, %2;" : "=f"(lo), "=f"(hi) : "l"(p));
    return lo + hi;
}

__global__ __launch_bounds__(THREADS, 1)
void win_attn_kernel(const float* __restrict__ x,
                     const float* __restrict__ mask,
                     const float* __restrict__ W,        // (384,128)
                     const float* __restrict__ bvec,     // (384,)
                     const float* __restrict__ rel_table,// (169,4)
                     float* __restrict__ out)
{
    extern __shared__ float sm[];
    float* xs     = sm + X_OFF;
    float* q_s    = sm + Q_OFF;
    float* kT_s   = sm + KT_OFF;
    float* v_s    = sm + V_OFF;
    float* mask_s = sm + MASK_OFF;
    float* rel_s  = sm + REL_OFF;
    unsigned char* ridx_s = (unsigned char*)sm + RIDX_B;

    const int b = blockIdx.x;
    const int t = threadIdx.x;

    // ---- phase 0: stage x, mask, rel_table, rel indices (concurrent, no alias) ----
    {
        const float4* xg  = (const float4*)(x + (size_t)b * (N_TOK * DIM));
        float4*       xs4 = (float4*)xs;
        #pragma unroll
        for (int i = t; i < (N_TOK * DIM) / 4; i += THREADS) xs4[i] = xg[i];

        const float* mw = mask + (size_t)(b & (NWIN - 1)) * (N_TOK * N_TOK);
        for (int i = t; i < N_TOK * N_TOK; i += THREADS) {
            mask_s[i] = mw[i];
            const int n = i / N_TOK, m = i - n * N_TOK;
            const int dh = n / 7 - m / 7 + 6;
            const int dw = n % 7 - m % 7 + 6;
            ridx_s[i] = (unsigned char)(dh * 13 + dw);
        }
        for (int i = t; i < 169 * NHEADS; i += THREADS) rel_s[i] = rel_table[i];
    }
    __syncthreads();

    // ---- phase 1: QKV projection ----
    // thread t: column pair (c0, c0+1), row half. Halves overlap at row 24
    // (computed twice, identical value -> benign write race, no guards needed).
    {
        const int th   = (t < 192) ? t : (t - 192);
        const int half = (t < 192) ? 0 : 1;
        const int c0   = 2 * th;
        const int row0 = half * 24;          // 0..24 or 24..48

        unsigned long long acc[2][25];
        #pragma unroll
        for (int c = 0; c < 2; c++)
            #pragma unroll
            for (int r = 0; r < 25; r++) acc[c][r] = 0ULL;

        const ulonglong2* w0p = (const ulonglong2*)(W + (size_t)c0 * DIM);
        const ulonglong2* w1p = (const ulonglong2*)(W + (size_t)(c0 + 1) * DIM);
        const ulonglong2* xs2 = (const ulonglong2*)xs;   // [n*32 + kk] = 4 floats

        for (int kk = 0; kk < DIM / 4; kk++) {
            const ulonglong2 w0 = __ldg(&w0p[kk]);
            const ulonglong2 w1 = __ldg(&w1p[kk]);
            #pragma unroll
            for (int r = 0; r < 25; r++) {
                const ulonglong2 xv = xs2[(row0 + r) * (DIM / 4) + kk]; // LDS.128 bcast
                FFMA2(acc[0][r], xv.x, w0.x);
                FFMA2(acc[0][r], xv.y, w0.y);
                FFMA2(acc[1][r], xv.x, w1.x);
                FFMA2(acc[1][r], xv.y, w1.y);
            }
        }

        const float scale = 0.17677669529663687f;  // 1/sqrt(32) folded into q
        #pragma unroll
        for (int c = 0; c < 2; c++) {
            const int o     = c0 + c;
            const int h     = o / 96;
            const int rem   = o - h * 96;
            const int d     = rem / 3;
            const int which = rem - d * 3;
            const float bo  = bvec[o];
            #pragma unroll
            for (int r = 0; r < 25; r++) {
                const int n = row0 + r;
                const float val = hsum2(acc[c][r]) + bo;
                if (which == 0)      q_s [(h * N_TOK + n) * HD + d]    = val * scale;
                else if (which == 1) kT_s[(h * HD + d) * N_TOK + n]    = val;
                else                 v_s [(h * N_TOK + n) * HD + d]    = val;
            }
        }
    }
    __syncthreads();

    // ---- phase 2: attention, one warp per (head, row) ----
    const int lane = t & 31;
    const int wid  = t >> 5;
    const bool valid1 = (lane + 32) < N_TOK;
    float* outb = out + (size_t)b * (N_TOK * DIM);

    for (int r = wid; r < NHEADS * N_TOK; r += THREADS / 32) {
        const int h = r / N_TOK;
        const int n = r - h * N_TOK;
        const int m0 = lane;
        const int m1 = valid1 ? (lane + 32) : 0;

        const float* qrow = q_s + (h * N_TOK + n) * HD;
        const float* kTb  = kT_s + h * HD * N_TOK;

        float s0 = 0.f, s1 = 0.f;
        #pragma unroll
        for (int dd = 0; dd < HD; dd++) {
            const float qd = qrow[dd];
            s0 = fmaf(qd, kTb[dd * N_TOK + m0], s0);
            s1 = fmaf(qd, kTb[dd * N_TOK + m1], s1);
        }
        s0 += rel_s[(int)ridx_s[n * N_TOK + m0] * NHEADS + h] + mask_s[n * N_TOK + m0];
        if (valid1)
            s1 += rel_s[(int)ridx_s[n * N_TOK + lane + 32] * NHEADS + h]
                + mask_s[n * N_TOK + lane + 32];
        else
            s1 = -1e30f;

        float mx = fmaxf(s0, s1);
        #pragma unroll
        for (int off = 16; off; off >>= 1) mx = fmaxf(mx, __shfl_xor_sync(0xffffffffu, mx, off));
        float p0 = __expf(s0 - mx);
        float p1 = valid1 ? __expf(s1 - mx) : 0.f;
        float sum = p0 + p1;
        #pragma unroll
        for (int off = 16; off; off >>= 1) sum += __shfl_xor_sync(0xffffffffu, sum, off);
        const float inv = 1.0f / sum;
        p0 *= inv; p1 *= inv;

        float acc = 0.f;
        const float* vb = v_s + h * N_TOK * HD + lane;
        #pragma unroll
        for (int m = 0; m < N_TOK; m++) {
            const float pm = __shfl_sync(0xffffffffu, (m < 32) ? p0 : p1, m & 31);
            acc = fmaf(pm, vb[m * HD], acc);
        }
        outb[n * DIM + h * HD + lane] = acc;
    }
}

extern "C" void kernel_launch(void* const* d_in, const int* in_sizes, int n_in,
                              void* d_out, int out_size)
{
    const float* x    = (const float*)d_in[0];
    const float* mask = (const float*)d_in[1];
    const float* W    = (const float*)d_in[2];
    const float* bvec = (const float*)d_in[3];
    const float* rel  = (const float*)d_in[4];
    float* out = (float*)d_out;

    cudaFuncSetAttribute(win_attn_kernel,
                         cudaFuncAttributeMaxDynamicSharedMemorySize, SMEM_BYTES);
    win_attn_kernel<<<4096, THREADS, SMEM_BYTES>>>(x, mask, W, bvec, rel, out);
}

// round 6
// speedup vs baseline: 1.3216x; 1.3216x over previous
#include <cuda_runtime.h>
#include <cuda_bf16.h>
#include <cstdint>

#define N_TOK   49
#define NHEADS  4
#define NWIN    64
#define THREADS 384

// ---- smem byte offsets ----
#define OFF_BVEC 0         // 384 f32
#define OFF_REL  1536      // 676 f32 -> ends 4240
#define OFF_RIDX 4240      // 2401 u8 -> 6641
#define OFF_MASK 6644      // 2401 f32 -> 16248
#define OFF_XH   16384     // 4*8*32*4 u32 = 16384 B
#define OFF_XL   32768     // 16384 B
#define OFF_Q    49152     // 4*49*33*4 = 25872
#define OFF_KT   75024     // 4*32*49*4 = 25088
#define OFF_V    100112    // 25872
#define SMEM_TOTAL 125984

// W in fragment layout: [c8(48)][kc(8)][lane(32)][reg(2)] u32 (bf16 pairs)
__device__ __align__(16) uint32_t g_wfh[48 * 8 * 32 * 2];
__device__ __align__(16) uint32_t g_wfl[48 * 8 * 32 * 2];

__device__ __forceinline__ void mma16816(float* c, const uint32_t* a, const uint32_t* b) {
    asm volatile(
        "mma.sync.aligned.m16n8k16.row.col.f32.bf16.bf16.f32 "
        "{%0,%1,%2,%3}, {%4,%5,%6,%7}, {%8,%9}, {%0,%1,%2,%3};"
        : "+f"(c[0]), "+f"(c[1]), "+f"(c[2]), "+f"(c[3])
        : "r"(a[0]), "r"(a[1]), "r"(a[2]), "r"(a[3]), "r"(b[0]), "r"(b[1]));
}

// ---- prep: W (384x128 f32) -> bf16 hi/lo fragment-layout tiles ----
__global__ void prep_w(const float* __restrict__ W) {
    for (int i = blockIdx.x * blockDim.x + threadIdx.x; i < 384 * 64;
         i += gridDim.x * blockDim.x) {
        const int o = i >> 6, kp = i & 63, k = kp * 2;
        const float w0 = W[o * 128 + k], w1 = W[o * 128 + k + 1];
        const __nv_bfloat16 h0 = __float2bfloat16(w0), h1 = __float2bfloat16(w1);
        const __nv_bfloat16 l0 = __float2bfloat16(w0 - __bfloat162float(h0));
        const __nv_bfloat16 l1 = __float2bfloat16(w1 - __bfloat162float(h1));
        const uint32_t ph = (uint32_t)__bfloat16_as_ushort(h0)
                          | ((uint32_t)__bfloat16_as_ushort(h1) << 16);
        const uint32_t pl = (uint32_t)__bfloat16_as_ushort(l0)
                          | ((uint32_t)__bfloat16_as_ushort(l1) << 16);
        const int c8 = o >> 3, g = o & 7, kc = k >> 4, kk = k & 15;
        const int reg = (kk >= 8), j = (kk & 7) >> 1;
        const int pos = (((c8 * 8 + kc) * 32) + g * 4 + j) * 2 + reg;
        g_wfh[pos] = ph;
        g_wfl[pos] = pl;
    }
}

__global__ __launch_bounds__(THREADS, 1)
void win_attn_kernel(const float* __restrict__ x, const float* __restrict__ mask,
                     const float* __restrict__ bvec, const float* __restrict__ rel_table,
                     float* __restrict__ out)
{
    extern __shared__ char sm[];
    float* bvec_s = (float*)(sm + OFF_BVEC);
    float* rel_s  = (float*)(sm + OFF_REL);
    unsigned char* ridx_s = (unsigned char*)(sm + OFF_RIDX);
    float* mask_s = (float*)(sm + OFF_MASK);
    float* q_s    = (float*)(sm + OFF_Q);    // [h][n] stride 33
    float* kT_s   = (float*)(sm + OFF_KT);   // [h][d][n]
    float* v_s    = (float*)(sm + OFF_V);    // [h][n] stride 33

    const int t = threadIdx.x, wid = t >> 5, lane = t & 31;
    const int g = lane >> 2, tq = lane & 3;
    const int b = blockIdx.x;

    // ---- stage: small tables + zero x-frag pad ----
    for (int i = t; i < 384; i += THREADS) bvec_s[i] = bvec[i];
    for (int i = t; i < 676; i += THREADS) rel_s[i] = rel_table[i];
    {
        const float* mw = mask + (size_t)(b & (NWIN - 1)) * 2401;
        for (int i = t; i < 2401; i += THREADS) {
            mask_s[i] = mw[i];
            const int n = i / 49, m = i - n * 49;
            ridx_s[i] = (unsigned char)((n / 7 - m / 7 + 6) * 13 + (n % 7 - m % 7 + 6));
        }
        uint4 z = make_uint4(0, 0, 0, 0);
        uint4* xa = (uint4*)(sm + OFF_XH);
        for (int i = t; i < 2048; i += THREADS) xa[i] = z;  // covers XH+XL
    }
    __syncthreads();

    // ---- stage x (49x128 f32) -> bf16 hi/lo in mma fragment layout ----
    {
        const float4* xg = (const float4*)(x + (size_t)b * 6272);
        uint32_t* xh = (uint32_t*)(sm + OFF_XH);
        uint32_t* xl = (uint32_t*)(sm + OFF_XL);
        for (int i = t; i < 1568; i += THREADS) {
            const int n = i >> 5, k0 = (i & 31) * 4;
            const float4 v = xg[i];
            const __nv_bfloat16 h0 = __float2bfloat16(v.x), h1 = __float2bfloat16(v.y);
            const __nv_bfloat16 h2 = __float2bfloat16(v.z), h3 = __float2bfloat16(v.w);
            const __nv_bfloat16 l0 = __float2bfloat16(v.x - __bfloat162float(h0));
            const __nv_bfloat16 l1 = __float2bfloat16(v.y - __bfloat162float(h1));
            const __nv_bfloat16 l2 = __float2bfloat16(v.z - __bfloat162float(h2));
            const __nv_bfloat16 l3 = __float2bfloat16(v.w - __bfloat162float(h3));
            const uint32_t ph01 = (uint32_t)__bfloat16_as_ushort(h0) | ((uint32_t)__bfloat16_as_ushort(h1) << 16);
            const uint32_t ph23 = (uint32_t)__bfloat16_as_ushort(h2) | ((uint32_t)__bfloat16_as_ushort(h3) << 16);
            const uint32_t pl01 = (uint32_t)__bfloat16_as_ushort(l0) | ((uint32_t)__bfloat16_as_ushort(l1) << 16);
            const uint32_t pl23 = (uint32_t)__bfloat16_as_ushort(l2) | ((uint32_t)__bfloat16_as_ushort(l3) << 16);
            const int mt = n >> 4, r16 = n & 15, g8 = r16 & 7;
            const int kc = k0 >> 4, kk = k0 & 15;
            const int reg = (r16 >= 8 ? 1 : 0) + (kk >= 8 ? 2 : 0);
            const int j = (kk & 7) >> 1;
            const int base = (((mt * 8 + kc) * 32) + g8 * 4 + j) * 4 + reg;
            xh[base] = ph01; xh[base + 4] = ph23;   // j and j+1 lanes
            xl[base] = pl01; xl[base + 4] = pl23;
        }
    }
    __syncthreads();

    // ---- projection: warp tile 64 x 32 (M=64 rows, 32 cols at n0) ----
    {
        const int n0 = wid * 32;
        float c[4][4][4];
        #pragma unroll
        for (int mt = 0; mt < 4; mt++)
            #pragma unroll
            for (int nt = 0; nt < 4; nt++)
                #pragma unroll
                for (int e = 0; e < 4; e++) c[mt][nt][e] = 0.f;

        const uint2* wfh = (const uint2*)g_wfh;
        const uint2* wfl = (const uint2*)g_wfl;

        #pragma unroll
        for (int kc = 0; kc < 8; kc++) {
            uint4 ah[4], al[4];
            #pragma unroll
            for (int mt = 0; mt < 4; mt++) {
                ah[mt] = *(const uint4*)(sm + OFF_XH + ((((mt * 8 + kc) * 32) + lane) << 4));
                al[mt] = *(const uint4*)(sm + OFF_XL + ((((mt * 8 + kc) * 32) + lane) << 4));
            }
            uint2 bh[4], bl[4];
            #pragma unroll
            for (int nt = 0; nt < 4; nt++) {
                const int idx = ((wid * 4 + nt) * 8 + kc) * 32 + lane;
                bh[nt] = __ldg(&wfh[idx]);
                bl[nt] = __ldg(&wfl[idx]);
            }
            #pragma unroll
            for (int mt = 0; mt < 4; mt++)
                #pragma unroll
                for (int nt = 0; nt < 4; nt++) {
                    mma16816(c[mt][nt], (const uint32_t*)&ah[mt], (const uint32_t*)&bh[nt]);
                    mma16816(c[mt][nt], (const uint32_t*)&ah[mt], (const uint32_t*)&bl[nt]);
                    mma16816(c[mt][nt], (const uint32_t*)&al[mt], (const uint32_t*)&bh[nt]);
                }
        }

        // writeback: +bias, route to q (scaled) / kT / v
        const float scale = 0.17677669529663687f;  // 1/sqrt(32)
        #pragma unroll
        for (int mt = 0; mt < 4; mt++) {
            #pragma unroll
            for (int nt = 0; nt < 4; nt++) {
                #pragma unroll
                for (int e = 0; e < 4; e++) {
                    const int n = mt * 16 + g + (e >= 2 ? 8 : 0);
                    if (n >= N_TOK) continue;
                    const int o = n0 + nt * 8 + tq * 2 + (e & 1);
                    const float val = c[mt][nt][e] + bvec_s[o];
                    const int h = o / 96, rem = o - 96 * h;
                    const int d = rem / 3, which = rem - 3 * d;
                    if (which == 0)      q_s[(h * 49 + n) * 33 + d] = val * scale;
                    else if (which == 1) kT_s[(h * 32 + d) * 49 + n] = val;
                    else                 v_s[(h * 49 + n) * 33 + d] = val;
                }
            }
        }
    }
    __syncthreads();

    // ---- attention: one warp per (head, row n) ----
    const bool valid1 = (lane + 32) < N_TOK;
    for (int rr = wid; rr < NHEADS * N_TOK; rr += THREADS / 32) {
        const int h = rr / N_TOK;
        const int n = rr - h * N_TOK;
        const int m1 = valid1 ? (lane + 32) : 0;
        const float* qrow = q_s + (h * 49 + n) * 33;
        const float* kTb  = kT_s + h * 32 * 49;

        float s0 = 0.f, s1 = 0.f;
        #pragma unroll
        for (int dd = 0; dd < 32; dd++) {
            const float qd = qrow[dd];
            s0 = fmaf(qd, kTb[dd * 49 + lane], s0);
            s1 = fmaf(qd, kTb[dd * 49 + m1], s1);
        }
        s0 += rel_s[(int)ridx_s[n * 49 + lane] * NHEADS + h] + mask_s[n * 49 + lane];
        if (valid1)
            s1 += rel_s[(int)ridx_s[n * 49 + lane + 32] * NHEADS + h] + mask_s[n * 49 + lane + 32];
        else s1 = -1e30f;

        float mx = fmaxf(s0, s1);
        #pragma unroll
        for (int o = 16; o; o >>= 1) mx = fmaxf(mx, __shfl_xor_sync(~0u, mx, o));
        float p0 = __expf(s0 - mx);
        float p1 = valid1 ? __expf(s1 - mx) : 0.f;
        float sum = p0 + p1;
        #pragma unroll
        for (int o = 16; o; o >>= 1) sum += __shfl_xor_sync(~0u, sum, o);
        const float inv = 1.f / sum;
        p0 *= inv; p1 *= inv;

        float acc = 0.f;
        const float* vb = v_s + h * 49 * 33 + lane;
        #pragma unroll
        for (int m = 0; m < N_TOK; m++) {
            const float pm = __shfl_sync(~0u, (m < 32) ? p0 : p1, m & 31);
            acc = fmaf(pm, vb[m * 33], acc);
        }
        out[(size_t)b * 6272 + n * 128 + h * 32 + lane] = acc;
    }
}

extern "C" void kernel_launch(void* const* d_in, const int* in_sizes, int n_in,
                              void* d_out, int out_size)
{
    const float* x    = (const float*)d_in[0];
    const float* mask = (const float*)d_in[1];
    const float* W    = (const float*)d_in[2];
    const float* bvec = (const float*)d_in[3];
    const float* rel  = (const float*)d_in[4];
    float* out = (float*)d_out;

    prep_w<<<96, 256>>>(W);
    cudaFuncSetAttribute(win_attn_kernel,
                         cudaFuncAttributeMaxDynamicSharedMemorySize, SMEM_TOTAL);
    win_attn_kernel<<<4096, THREADS, SMEM_TOTAL>>>(x, mask, bvec, rel, out);
}

// round 7
// speedup vs baseline: 1.9525x; 1.4774x over previous
#include <cuda_runtime.h>
#include <cuda_bf16.h>
#include <cstdint>

#define N_TOK   49
#define NHEADS  4
#define NWIN    64
#define THREADS 448

typedef unsigned long long ull;

// ---- smem byte offsets ----
#define OFF_BVEC 0          // 384 f32
#define OFF_REL  1536       // 676 f32 -> 4240
#define OFF_RIDX 4240       // 2401 u8 -> 6641
#define OFF_MASK 6656       // 2*2401 f32 -> 25864
#define OFF_BIG  25984
#define OFF_Q0   (OFF_BIG)            // 4*49*33*4 = 25872
#define OFF_K0   (OFF_Q0 + 25872)     // 4*49*32*4 = 25088 (row-major, 128B rows)
#define OFF_V0   (OFF_K0 + 25088)     // 25088
#define OFF_Q1   (OFF_V0 + 25088)     // 25872
#define OFF_K1   (OFF_Q1 + 25872)     // 25088
#define OFF_V1   (OFF_K1 + 25088)     // 25088
#define SMEM_TOTAL (OFF_V1 + 25088)   // 178080
// x-fragment staging aliases the win1 block (written only after post-MMA sync)
#define OFF_XH   (OFF_Q1)             // 8*8*32*16 = 32768
#define OFF_XL   (OFF_Q1 + 32768)     // 32768 (ends 167568 < SMEM_TOTAL)

// W in fragment layout: [c8(48)][kc(8)][lane(32)][reg(2)] u32 (bf16 pairs)
__device__ __align__(16) uint32_t g_wfh[48 * 8 * 32 * 2];
__device__ __align__(16) uint32_t g_wfl[48 * 8 * 32 * 2];

#define FFMA2(acc, a, b) \
    asm("fma.rn.f32x2 %0, %1, %2, %0;" : "+l"(acc) : "l"(a), "l"(b))
#define DUP2(d, f) \
    asm("mov.b64 %0, {%1, %1};" : "=l"(d) : "f"(f))
#define PACK2(d, lo, hi) \
    asm("mov.b64 %0, {%1, %2};" : "=l"(d) : "f"(lo), "f"(hi))

__device__ __forceinline__ float hsum2(ull p) {
    float lo, hi;
    asm("mov.b64 {%0, %1}, %2;" : "=f"(lo), "=f"(hi) : "l"(p));
    return lo + hi;
}

__device__ __forceinline__ void mma16816(float* c, const uint32_t* a, const uint32_t* b) {
    asm volatile(
        "mma.sync.aligned.m16n8k16.row.col.f32.bf16.bf16.f32 "
        "{%0,%1,%2,%3}, {%4,%5,%6,%7}, {%8,%9}, {%0,%1,%2,%3};"
        : "+f"(c[0]), "+f"(c[1]), "+f"(c[2]), "+f"(c[3])
        : "r"(a[0]), "r"(a[1]), "r"(a[2]), "r"(a[3]), "r"(b[0]), "r"(b[1]));
}

// ---- prep: W (384x128 f32) -> bf16 hi/lo fragment-layout tiles ----
__global__ void prep_w(const float* __restrict__ W) {
    for (int i = blockIdx.x * blockDim.x + threadIdx.x; i < 384 * 64;
         i += gridDim.x * blockDim.x) {
        const int o = i >> 6, kp = i & 63, k = kp * 2;
        const float w0 = W[o * 128 + k], w1 = W[o * 128 + k + 1];
        const __nv_bfloat16 h0 = __float2bfloat16(w0), h1 = __float2bfloat16(w1);
        const __nv_bfloat16 l0 = __float2bfloat16(w0 - __bfloat162float(h0));
        const __nv_bfloat16 l1 = __float2bfloat16(w1 - __bfloat162float(h1));
        const uint32_t ph = (uint32_t)__bfloat16_as_ushort(h0)
                          | ((uint32_t)__bfloat16_as_ushort(h1) << 16);
        const uint32_t pl = (uint32_t)__bfloat16_as_ushort(l0)
                          | ((uint32_t)__bfloat16_as_ushort(l1) << 16);
        const int c8 = o >> 3, g = o & 7, kc = k >> 4, kk = k & 15;
        const int reg = (kk >= 8), j = (kk & 7) >> 1;
        const int pos = (((c8 * 8 + kc) * 32) + g * 4 + j) * 2 + reg;
        g_wfh[pos] = ph;
        g_wfl[pos] = pl;
    }
}

__device__ __forceinline__ void proj_mma(char* sm, int wid, int lane, int pass,
                                         float c[4][4][4]) {
    #pragma unroll
    for (int mt = 0; mt < 4; mt++)
        #pragma unroll
        for (int nt = 0; nt < 4; nt++)
            #pragma unroll
            for (int e = 0; e < 4; e++) c[mt][nt][e] = 0.f;

    const uint2* wfh = (const uint2*)g_wfh;
    const uint2* wfl = (const uint2*)g_wfl;
    #pragma unroll
    for (int kc = 0; kc < 8; kc++) {
        uint4 ah[4], al[4];
        #pragma unroll
        for (int mt = 0; mt < 4; mt++) {
            const int idx = (((pass * 4 + mt) * 8 + kc) * 32 + lane) << 4;
            ah[mt] = *(const uint4*)(sm + OFF_XH + idx);
            al[mt] = *(const uint4*)(sm + OFF_XL + idx);
        }
        uint2 bh[4], bl[4];
        #pragma unroll
        for (int nt = 0; nt < 4; nt++) {
            const int idx = ((wid * 4 + nt) * 8 + kc) * 32 + lane;
            bh[nt] = __ldg(&wfh[idx]);
            bl[nt] = __ldg(&wfl[idx]);
        }
        #pragma unroll
        for (int mt = 0; mt < 4; mt++)
            #pragma unroll
            for (int nt = 0; nt < 4; nt++) {
                mma16816(c[mt][nt], (const uint32_t*)&ah[mt], (const uint32_t*)&bh[nt]);
                mma16816(c[mt][nt], (const uint32_t*)&ah[mt], (const uint32_t*)&bl[nt]);
                mma16816(c[mt][nt], (const uint32_t*)&al[mt], (const uint32_t*)&bh[nt]);
            }
    }
}

__device__ __forceinline__ void proj_wb(char* sm, int wid, int lane, int win,
                                        float c[4][4][4], const float* bvec_s) {
    float* qb = (float*)(sm + (win ? OFF_Q1 : OFF_Q0));
    float* kb = (float*)(sm + (win ? OFF_K1 : OFF_K0));
    float* vb = (float*)(sm + (win ? OFF_V1 : OFF_V0));
    const int g = lane >> 2, tq = lane & 3, n0 = wid * 32;
    const float scale = 0.17677669529663687f;  // 1/sqrt(32)
    #pragma unroll
    for (int mt = 0; mt < 4; mt++)
        #pragma unroll
        for (int nt = 0; nt < 4; nt++)
            #pragma unroll
            for (int e = 0; e < 4; e++) {
                const int n = mt * 16 + g + (e >= 2 ? 8 : 0);
                if (n >= N_TOK) continue;
                const int o = n0 + nt * 8 + tq * 2 + (e & 1);
                const float val = c[mt][nt][e] + bvec_s[o];
                const int h = o / 96, rem = o - 96 * h;
                const int d = rem / 3, which = rem - 3 * d;
                if (which == 0)      qb[(h * 49 + n) * 33 + d] = val * scale;
                else if (which == 1) kb[(h * 49 + n) * 32 + d] = val;
                else                 vb[(h * 49 + n) * 32 + d] = val;
            }
}

__global__ __launch_bounds__(THREADS, 1)
void win_attn_kernel(const float* __restrict__ x, const float* __restrict__ mask,
                     const float* __restrict__ bvec, const float* __restrict__ rel_table,
                     float* __restrict__ out)
{
    extern __shared__ char sm[];
    float* bvec_s = (float*)(sm + OFF_BVEC);
    float* rel_s  = (float*)(sm + OFF_REL);
    unsigned char* ridx_s = (unsigned char*)(sm + OFF_RIDX);
    float* mask_s = (float*)(sm + OFF_MASK);

    const int t = threadIdx.x, wid = t >> 5, lane = t & 31;
    const int b0 = 2 * blockIdx.x;

    // ---- stage small tables + zero x-fragment buffers ----
    for (int i = t; i < 384; i += THREADS) bvec_s[i] = bvec[i];
    for (int i = t; i < 676; i += THREADS) rel_s[i] = rel_table[i];
    {
        const float* mw = mask + (size_t)(b0 & (NWIN - 1)) * 2401;
        for (int i = t; i < 2 * 2401; i += THREADS) mask_s[i] = mw[i];
        for (int i = t; i < 2401; i += THREADS) {
            const int n = i / 49, m = i - n * 49;
            ridx_s[i] = (unsigned char)((n / 7 - m / 7 + 6) * 13 + (n % 7 - m % 7 + 6));
        }
        uint4 z = make_uint4(0, 0, 0, 0);
        uint4* xa = (uint4*)(sm + OFF_XH);
        for (int i = t; i < 4096; i += THREADS) xa[i] = z;  // XH + XL
    }
    __syncthreads();

    // ---- stage x (2 windows) -> bf16 hi/lo in mma fragment layout (M=128) ----
    {
        const float4* xg = (const float4*)(x + (size_t)b0 * 6272);
        uint32_t* xh = (uint32_t*)(sm + OFF_XH);
        uint32_t* xl = (uint32_t*)(sm + OFF_XL);
        for (int i = t; i < 2 * 1568; i += THREADS) {
            const int win = i / 1568, j = i - win * 1568;
            const int n = j >> 5, k0 = (j & 31) * 4;
            const int r = win * 64 + n;
            const float4 v = xg[i];
            const __nv_bfloat16 h0 = __float2bfloat16(v.x), h1 = __float2bfloat16(v.y);
            const __nv_bfloat16 h2 = __float2bfloat16(v.z), h3 = __float2bfloat16(v.w);
            const __nv_bfloat16 l0 = __float2bfloat16(v.x - __bfloat162float(h0));
            const __nv_bfloat16 l1 = __float2bfloat16(v.y - __bfloat162float(h1));
            const __nv_bfloat16 l2 = __float2bfloat16(v.z - __bfloat162float(h2));
            const __nv_bfloat16 l3 = __float2bfloat16(v.w - __bfloat162float(h3));
            const uint32_t ph01 = (uint32_t)__bfloat16_as_ushort(h0) | ((uint32_t)__bfloat16_as_ushort(h1) << 16);
            const uint32_t ph23 = (uint32_t)__bfloat16_as_ushort(h2) | ((uint32_t)__bfloat16_as_ushort(h3) << 16);
            const uint32_t pl01 = (uint32_t)__bfloat16_as_ushort(l0) | ((uint32_t)__bfloat16_as_ushort(l1) << 16);
            const uint32_t pl23 = (uint32_t)__bfloat16_as_ushort(l2) | ((uint32_t)__bfloat16_as_ushort(l3) << 16);
            const int mt = r >> 4, r16 = r & 15, g8 = r16 & 7;
            const int kc = k0 >> 4, kk = k0 & 15;
            const int reg = (r16 >= 8 ? 1 : 0) + (kk >= 8 ? 2 : 0);
            const int jj = (kk & 7) >> 1;
            const int base = (((mt * 8 + kc) * 32) + g8 * 4 + jj) * 4 + reg;
            xh[base] = ph01; xh[base + 4] = ph23;
            xl[base] = pl01; xl[base + 4] = pl23;
        }
    }
    __syncthreads();

    // ---- projection: pass 0 (win0), then pass 1 (win1, deferred writeback) ----
    float c[4][4][4];
    if (wid < 12) {
        proj_mma(sm, wid, lane, 0, c);
        proj_wb(sm, wid, lane, 0, c, bvec_s);   // q0/k0/v0 disjoint from XH/XL
        proj_mma(sm, wid, lane, 1, c);
    }
    __syncthreads();          // all XH/XL reads done
    if (wid < 12) proj_wb(sm, wid, lane, 1, c, bvec_s);
    __syncthreads();          // q/k/v ready

    // ---- attention: one thread per (win, head, row) ----
    if (t < 2 * NHEADS * N_TOK) {
        const int wh = t / 49;          // 0..7
        const int n  = t - wh * 49;
        const int win = wh >> 2, h = wh & 3;

        const float* qrow = (const float*)(sm + (win ? OFF_Q1 : OFF_Q0)) + (h * 49 + n) * 33;
        const ulonglong2* kb = (const ulonglong2*)(sm + (win ? OFF_K1 : OFF_K0) + h * 49 * 128);
        const ulonglong2* vb = (const ulonglong2*)(sm + (win ? OFF_V1 : OFF_V0) + h * 49 * 128);
        const float* msk = (const float*)(sm + OFF_MASK + win * 9604) + n * 49;
        const unsigned char* rix = ridx_s + n * 49;

        ull qp[16];
        #pragma unroll
        for (int j = 0; j < 16; j++) PACK2(qp[j], qrow[2 * j], qrow[2 * j + 1]);

        float s[49];
        #pragma unroll
        for (int m = 0; m < 49; m++) {
            ull acc = 0ULL;
            const ulonglong2* kr = kb + m * 8;
            #pragma unroll
            for (int j = 0; j < 8; j++) {
                const ulonglong2 kp = kr[j];
                FFMA2(acc, qp[2 * j], kp.x);
                FFMA2(acc, qp[2 * j + 1], kp.y);
            }
            s[m] = hsum2(acc) + rel_s[(int)rix[m] * NHEADS + h] + msk[m];
        }

        float mx = s[0];
        #pragma unroll
        for (int m = 1; m < 49; m++) mx = fmaxf(mx, s[m]);
        float sum = 0.f;
        #pragma unroll
        for (int m = 0; m < 49; m++) { s[m] = __expf(s[m] - mx); sum += s[m]; }
        const float inv = 1.f / sum;

        ull o[16];
        #pragma unroll
        for (int j = 0; j < 16; j++) o[j] = 0ULL;
        #pragma unroll
        for (int m = 0; m < 49; m++) {
            ull pm; DUP2(pm, s[m]);
            const ulonglong2* vr = vb + m * 8;
            #pragma unroll
            for (int j = 0; j < 8; j++) {
                const ulonglong2 vp = vr[j];
                FFMA2(o[2 * j], pm, vp.x);
                FFMA2(o[2 * j + 1], pm, vp.y);
            }
        }
        ull inv2; DUP2(inv2, inv);
        #pragma unroll
        for (int j = 0; j < 16; j++) { ull z = 0ULL; FFMA2(z, o[j], inv2); o[j] = z; }

        ulonglong2* og = (ulonglong2*)(out + (size_t)(b0 + win) * 6272 + n * 128 + h * 32);
        #pragma unroll
        for (int i = 0; i < 8; i++) {
            ulonglong2 w; w.x = o[2 * i]; w.y = o[2 * i + 1];
            og[i] = w;
        }
    }
}

extern "C" void kernel_launch(void* const* d_in, const int* in_sizes, int n_in,
                              void* d_out, int out_size)
{
    const float* x    = (const float*)d_in[0];
    const float* mask = (const float*)d_in[1];
    const float* W    = (const float*)d_in[2];
    const float* bvec = (const float*)d_in[3];
    const float* rel  = (const float*)d_in[4];
    float* out = (float*)d_out;

    prep_w<<<96, 256>>>(W);
    cudaFuncSetAttribute(win_attn_kernel,
                         cudaFuncAttributeMaxDynamicSharedMemorySize, SMEM_TOTAL);
    win_attn_kernel<<<2048, THREADS, SMEM_TOTAL>>>(x, mask, bvec, rel, out);
}

// round 8
// speedup vs baseline: 2.0769x; 1.0637x over previous
#include <cuda_runtime.h>
#include <cuda_bf16.h>
#include <cstdint>

#define N_TOK   49
#define NHEADS  4
#define NWIN    64
#define THREADS 416

typedef unsigned long long ull;

// ---- smem byte offsets ----
// [0, 32768): phase-1 = x fragments (XH 16K | XL 16K); phase-2 = mask/ridx/rel
#define OFF_XH   0
#define OFF_XL   16384
#define OFF_MASK 0          // 2401 f32 -> 9604
#define OFF_RIDX 9604       // 2401 u8  -> 12005
#define OFF_REL  12008      // 676 f32  -> 14712
#define OFF_BVEC 32768      // 384 f32
#define OFF_Q    34304      // 196 rows x 33 f32 = 25872
#define OFF_K    60176      // 196 rows x 32 f32 = 25088 (128B rows)
#define OFF_V    85264      // 25088
#define SMEM_TOTAL 110352

// W in fragment layout: [c8(48)][kc(8)][lane(32)][reg(2)] u32 (bf16 pairs)
__device__ __align__(16) uint32_t g_wfh[48 * 8 * 32 * 2];
__device__ __align__(16) uint32_t g_wfl[48 * 8 * 32 * 2];

#define FFMA2(acc, a, b) \
    asm("fma.rn.f32x2 %0, %1, %2, %0;" : "+l"(acc) : "l"(a), "l"(b))
#define DUP2(d, f) \
    asm("mov.b64 %0, {%1, %1};" : "=l"(d) : "f"(f))
#define PACK2(d, lo, hi) \
    asm("mov.b64 %0, {%1, %2};" : "=l"(d) : "f"(lo), "f"(hi))

__device__ __forceinline__ float hsum2(ull p) {
    float lo, hi;
    asm("mov.b64 {%0, %1}, %2;" : "=f"(lo), "=f"(hi) : "l"(p));
    return lo + hi;
}

__device__ __forceinline__ void mma16816(float* c, const uint32_t* a, const uint32_t* b) {
    asm volatile(
        "mma.sync.aligned.m16n8k16.row.col.f32.bf16.bf16.f32 "
        "{%0,%1,%2,%3}, {%4,%5,%6,%7}, {%8,%9}, {%0,%1,%2,%3};"
        : "+f"(c[0]), "+f"(c[1]), "+f"(c[2]), "+f"(c[3])
        : "r"(a[0]), "r"(a[1]), "r"(a[2]), "r"(a[3]), "r"(b[0]), "r"(b[1]));
}

// ---- prep: W (384x128 f32) -> bf16 hi/lo fragment-layout tiles ----
__global__ void prep_w(const float* __restrict__ W) {
    for (int i = blockIdx.x * blockDim.x + threadIdx.x; i < 384 * 64;
         i += gridDim.x * blockDim.x) {
        const int o = i >> 6, kp = i & 63, k = kp * 2;
        const float w0 = W[o * 128 + k], w1 = W[o * 128 + k + 1];
        const __nv_bfloat16 h0 = __float2bfloat16(w0), h1 = __float2bfloat16(w1);
        const __nv_bfloat16 l0 = __float2bfloat16(w0 - __bfloat162float(h0));
        const __nv_bfloat16 l1 = __float2bfloat16(w1 - __bfloat162float(h1));
        const uint32_t ph = (uint32_t)__bfloat16_as_ushort(h0)
                          | ((uint32_t)__bfloat16_as_ushort(h1) << 16);
        const uint32_t pl = (uint32_t)__bfloat16_as_ushort(l0)
                          | ((uint32_t)__bfloat16_as_ushort(l1) << 16);
        const int c8 = o >> 3, g = o & 7, kc = k >> 4, kk = k & 15;
        const int reg = (kk >= 8), j = (kk & 7) >> 1;
        const int pos = (((c8 * 8 + kc) * 32) + g * 4 + j) * 2 + reg;
        g_wfh[pos] = ph;
        g_wfl[pos] = pl;
    }
}

__global__ __launch_bounds__(THREADS, 2)
void win_attn_kernel(const float* __restrict__ x, const float* __restrict__ mask,
                     const float* __restrict__ bvec, const float* __restrict__ rel_table,
                     float* __restrict__ out)
{
    extern __shared__ char sm[];
    float* bvec_s = (float*)(sm + OFF_BVEC);

    const int t = threadIdx.x, wid = t >> 5, lane = t & 31;
    const int b = blockIdx.x;

    // ---- phase 0: stage bvec + x -> bf16 hi/lo mma fragments (M=64, pad zeroed) ----
    for (int i = t; i < 384; i += THREADS) bvec_s[i] = bvec[i];
    {
        const float4* xg = (const float4*)(x + (size_t)b * 6272);
        uint32_t* xh = (uint32_t*)(sm + OFF_XH);
        uint32_t* xl = (uint32_t*)(sm + OFF_XL);
        for (int i = t; i < 64 * 32; i += THREADS) {
            const int r = i >> 5, k0 = (i & 31) * 4;
            float4 v = make_float4(0.f, 0.f, 0.f, 0.f);
            if (r < N_TOK) v = xg[r * 32 + (i & 31)];
            const __nv_bfloat16 h0 = __float2bfloat16(v.x), h1 = __float2bfloat16(v.y);
            const __nv_bfloat16 h2 = __float2bfloat16(v.z), h3 = __float2bfloat16(v.w);
            const __nv_bfloat16 l0 = __float2bfloat16(v.x - __bfloat162float(h0));
            const __nv_bfloat16 l1 = __float2bfloat16(v.y - __bfloat162float(h1));
            const __nv_bfloat16 l2 = __float2bfloat16(v.z - __bfloat162float(h2));
            const __nv_bfloat16 l3 = __float2bfloat16(v.w - __bfloat162float(h3));
            const uint32_t ph01 = (uint32_t)__bfloat16_as_ushort(h0) | ((uint32_t)__bfloat16_as_ushort(h1) << 16);
            const uint32_t ph23 = (uint32_t)__bfloat16_as_ushort(h2) | ((uint32_t)__bfloat16_as_ushort(h3) << 16);
            const uint32_t pl01 = (uint32_t)__bfloat16_as_ushort(l0) | ((uint32_t)__bfloat16_as_ushort(l1) << 16);
            const uint32_t pl23 = (uint32_t)__bfloat16_as_ushort(l2) | ((uint32_t)__bfloat16_as_ushort(l3) << 16);
            const int mt = r >> 4, r16 = r & 15, g8 = r16 & 7;
            const int kc = k0 >> 4, kk = k0 & 15;
            const int reg = (r16 >= 8 ? 1 : 0) + (kk >= 8 ? 2 : 0);
            const int jj = (kk & 7) >> 1;
            const int base = (((mt * 8 + kc) * 32) + g8 * 4 + jj) * 4 + reg;
            xh[base] = ph01; xh[base + 4] = ph23;
            xl[base] = pl01; xl[base + 4] = pl23;
        }
    }
    __syncthreads();

    // ---- phase 1: projection, warp tile 64x16, 24 tiles over 13 warps ----
    {
        const int g = lane >> 2, tq = lane & 3;
        const float scale = 0.17677669529663687f;  // 1/sqrt(32)
        float* qb = (float*)(sm + OFF_Q);
        float* kb = (float*)(sm + OFF_K);
        float* vb = (float*)(sm + OFF_V);
        const uint2* wfh = (const uint2*)g_wfh;
        const uint2* wfl = (const uint2*)g_wfl;

        for (int tl = wid; tl < 24; tl += THREADS / 32) {
            float c[4][2][4];
            #pragma unroll
            for (int mt = 0; mt < 4; mt++)
                #pragma unroll
                for (int nt = 0; nt < 2; nt++)
                    #pragma unroll
                    for (int e = 0; e < 4; e++) c[mt][nt][e] = 0.f;

            #pragma unroll
            for (int kc = 0; kc < 8; kc++) {
                uint4 ah[4], al[4];
                #pragma unroll
                for (int mt = 0; mt < 4; mt++) {
                    const int idx = (((mt * 8 + kc) * 32) + lane) << 4;
                    ah[mt] = *(const uint4*)(sm + OFF_XH + idx);
                    al[mt] = *(const uint4*)(sm + OFF_XL + idx);
                }
                uint2 bh[2], bl[2];
                #pragma unroll
                for (int nt = 0; nt < 2; nt++) {
                    const int idx = ((tl * 2 + nt) * 8 + kc) * 32 + lane;
                    bh[nt] = __ldg(&wfh[idx]);
                    bl[nt] = __ldg(&wfl[idx]);
                }
                #pragma unroll
                for (int mt = 0; mt < 4; mt++)
                    #pragma unroll
                    for (int nt = 0; nt < 2; nt++) {
                        mma16816(c[mt][nt], (const uint32_t*)&ah[mt], (const uint32_t*)&bh[nt]);
                        mma16816(c[mt][nt], (const uint32_t*)&ah[mt], (const uint32_t*)&bl[nt]);
                        mma16816(c[mt][nt], (const uint32_t*)&al[mt], (const uint32_t*)&bh[nt]);
                    }
            }
            // writeback (+bias, route) — q/k/v disjoint from frag area
            #pragma unroll
            for (int mt = 0; mt < 4; mt++)
                #pragma unroll
                for (int nt = 0; nt < 2; nt++)
                    #pragma unroll
                    for (int e = 0; e < 4; e++) {
                        const int n = mt * 16 + g + (e >= 2 ? 8 : 0);
                        if (n >= N_TOK) continue;
                        const int o = tl * 16 + nt * 8 + tq * 2 + (e & 1);
                        const float val = c[mt][nt][e] + bvec_s[o];
                        const int h = o / 96, rem = o - 96 * h;
                        const int d = rem / 3, which = rem - 3 * d;
                        if (which == 0)      qb[(h * 49 + n) * 33 + d] = val * scale;
                        else if (which == 1) kb[(h * 49 + n) * 32 + d] = val;
                        else                 vb[(h * 49 + n) * 32 + d] = val;
                    }
        }
    }
    __syncthreads();

    // ---- phase 2: mask/ridx/rel into (now dead) fragment area ----
    {
        float* mask_s = (float*)(sm + OFF_MASK);
        unsigned char* ridx_s = (unsigned char*)(sm + OFF_RIDX);
        float* rel_s = (float*)(sm + OFF_REL);
        const float* mw = mask + (size_t)(b & (NWIN - 1)) * 2401;
        for (int i = t; i < 2401; i += THREADS) {
            mask_s[i] = mw[i];
            const int n = i / 49, m = i - n * 49;
            ridx_s[i] = (unsigned char)((n / 7 - m / 7 + 6) * 13 + (n % 7 - m % 7 + 6));
        }
        for (int i = t; i < 676; i += THREADS) rel_s[i] = rel_table[i];
    }
    __syncthreads();

    // ---- phase 3: attention, thread PAIR per (head, row): split m, then split d ----
    if (t < 2 * NHEADS * N_TOK) {
        const float* mask_s = (const float*)(sm + OFF_MASK);
        const unsigned char* ridx_s = (const unsigned char*)(sm + OFF_RIDX);
        const float* rel_s = (const float*)(sm + OFF_REL);

        const int rowi = t >> 1, half = t & 1;
        const int h = rowi / 49, n = rowi - h * 49;

        const float* qrow = (const float*)(sm + OFF_Q) + (h * 49 + n) * 33;
        const ulonglong2* kb = (const ulonglong2*)(sm + OFF_K + h * 49 * 128);
        const ulonglong2* vb = (const ulonglong2*)(sm + OFF_V + h * 49 * 128);
        const float* msk = mask_s + n * 49;
        const unsigned char* rix = ridx_s + n * 49;

        ull qp[16];
        #pragma unroll
        for (int j = 0; j < 16; j++) PACK2(qp[j], qrow[2 * j], qrow[2 * j + 1]);

        // phase A: scores for m = 2*mm + half
        float s[25];
        #pragma unroll
        for (int mm = 0; mm < 25; mm++) {
            const int m = 2 * mm + half;
            if (m < 49) {
                ull acc = 0ULL;
                const ulonglong2* kr = kb + m * 8;
                #pragma unroll
                for (int j = 0; j < 8; j++) {
                    const ulonglong2 kp = kr[j];
                    FFMA2(acc, qp[2 * j], kp.x);
                    FFMA2(acc, qp[2 * j + 1], kp.y);
                }
                s[mm] = hsum2(acc) + rel_s[(int)rix[m] * NHEADS + h] + msk[m];
            } else {
                s[mm] = -1e30f;
            }
        }
        // pair-combined softmax
        float mx = s[0];
        #pragma unroll
        for (int mm = 1; mm < 25; mm++) mx = fmaxf(mx, s[mm]);
        mx = fmaxf(mx, __shfl_xor_sync(~0u, mx, 1));
        float sum = 0.f;
        #pragma unroll
        for (int mm = 0; mm < 25; mm++) { s[mm] = __expf(s[mm] - mx); sum += s[mm]; }
        sum += __shfl_xor_sync(~0u, sum, 1);
        const float inv = 1.f / sum;
        #pragma unroll
        for (int mm = 0; mm < 25; mm++) s[mm] *= inv;   // s[] now = p

        // phase B: this thread accumulates dims [half*16, half*16+16)
        ull o[8];
        #pragma unroll
        for (int j = 0; j < 8; j++) o[j] = 0ULL;
        const int base = (lane & ~1);
        #pragma unroll
        for (int m = 0; m < 49; m++) {
            const float pv = __shfl_sync(~0u, s[m >> 1], base | (m & 1));
            ull pm; DUP2(pm, pv);
            const ulonglong2* vr = vb + m * 8 + half * 4;
            #pragma unroll
            for (int j = 0; j < 4; j++) {
                const ulonglong2 vp = vr[j];
                FFMA2(o[2 * j], pm, vp.x);
                FFMA2(o[2 * j + 1], pm, vp.y);
            }
        }
        ulonglong2* og = (ulonglong2*)(out + (size_t)b * 6272 + n * 128 + h * 32 + half * 16);
        #pragma unroll
        for (int i = 0; i < 4; i++) {
            ulonglong2 w; w.x = o[2 * i]; w.y = o[2 * i + 1];
            og[i] = w;
        }
    }
}

extern "C" void kernel_launch(void* const* d_in, const int* in_sizes, int n_in,
                              void* d_out, int out_size)
{
    const float* x    = (const float*)d_in[0];
    const float* mask = (const float*)d_in[1];
    const float* W    = (const float*)d_in[2];
    const float* bvec = (const float*)d_in[3];
    const float* rel  = (const float*)d_in[4];
    float* out = (float*)d_out;

    prep_w<<<96, 256>>>(W);
    cudaFuncSetAttribute(win_attn_kernel,
                         cudaFuncAttributeMaxDynamicSharedMemorySize, SMEM_TOTAL);
    win_attn_kernel<<<4096, THREADS, SMEM_TOTAL>>>(x, mask, bvec, rel, out);
}

// round 10
// speedup vs baseline: 2.7486x; 1.3234x over previous
#include <cuda_runtime.h>
#include <cuda_bf16.h>
#include <cstdint>

#define N_TOK   49
#define NHEADS  4
#define NWIN    64
#define THREADS 512

// ---- smem byte offsets ----
#define OFF_XH   0          // 16384
#define OFF_XL   16384      // 16384
#define OFF_QFH  32768      // 16384  q A-frags hi  [h][mt4][kc2][lane][reg4] u32
#define OFF_QFL  49152      // 16384
#define OFF_KFH  65536      // 14336  k B-frags hi  [h][nt7][kc2][lane][reg2] u32
#define OFF_KFL  79872      // 14336
#define OFF_VFH  94208      // 16384  v B-frags hi  [h][kck4][ntd4][lane][reg2] u32
#define OFF_VFL  110592     // 16384
#define OFF_MASK 126976     // 2401 f32
#define OFF_RIDX 136580     // 2401 u8
#define OFF_REL  139000     // 676 f32
#define OFF_BVEC 141704     // 384 f32
#define SMEM_TOTAL 143240

// W in fragment layout: [c8(48)][kc(8)][lane(32)][reg(2)] u32 (bf16 pairs)
__device__ __align__(16) uint32_t g_wfh[48 * 8 * 32 * 2];
__device__ __align__(16) uint32_t g_wfl[48 * 8 * 32 * 2];

__device__ __forceinline__ void mma16816(float* c, const uint32_t* a, const uint32_t* b) {
    asm volatile(
        "mma.sync.aligned.m16n8k16.row.col.f32.bf16.bf16.f32 "
        "{%0,%1,%2,%3}, {%4,%5,%6,%7}, {%8,%9}, {%0,%1,%2,%3};"
        : "+f"(c[0]), "+f"(c[1]), "+f"(c[2]), "+f"(c[3])
        : "r"(a[0]), "r"(a[1]), "r"(a[2]), "r"(a[3]), "r"(b[0]), "r"(b[1]));
}

__device__ __forceinline__ void split_bf16(float v, __nv_bfloat16& h, __nv_bfloat16& l) {
    h = __float2bfloat16(v);
    l = __float2bfloat16(v - __bfloat162float(h));
}

__device__ __forceinline__ void pack_hl(float a, float b, uint32_t& ph, uint32_t& pl) {
    __nv_bfloat16 ha, la, hb, lb;
    split_bf16(a, ha, la);
    split_bf16(b, hb, lb);
    ph = (uint32_t)__bfloat16_as_ushort(ha) | ((uint32_t)__bfloat16_as_ushort(hb) << 16);
    pl = (uint32_t)__bfloat16_as_ushort(la) | ((uint32_t)__bfloat16_as_ushort(lb) << 16);
}

// ---- prep: W (384x128 f32) -> bf16 hi/lo fragment-layout tiles ----
__global__ void prep_w(const float* __restrict__ W) {
    for (int i = blockIdx.x * blockDim.x + threadIdx.x; i < 384 * 64;
         i += gridDim.x * blockDim.x) {
        const int o = i >> 6, kp = i & 63, k = kp * 2;
        const float w0 = W[o * 128 + k], w1 = W[o * 128 + k + 1];
        __nv_bfloat16 h0, l0, h1, l1;
        split_bf16(w0, h0, l0);
        split_bf16(w1, h1, l1);
        const uint32_t ph = (uint32_t)__bfloat16_as_ushort(h0)
                          | ((uint32_t)__bfloat16_as_ushort(h1) << 16);
        const uint32_t pl = (uint32_t)__bfloat16_as_ushort(l0)
                          | ((uint32_t)__bfloat16_as_ushort(l1) << 16);
        const int c8 = o >> 3, g = o & 7, kc = k >> 4, kk = k & 15;
        const int reg = (kk >= 8), j = (kk & 7) >> 1;
        const int pos = (((c8 * 8 + kc) * 32) + g * 4 + j) * 2 + reg;
        g_wfh[pos] = ph;
        g_wfl[pos] = pl;
    }
}

__global__ __launch_bounds__(THREADS, 1)
void win_attn_kernel(const float* __restrict__ x, const float* __restrict__ mask,
                     const float* __restrict__ bvec, const float* __restrict__ rel_table,
                     float* __restrict__ out)
{
    extern __shared__ char sm[];
    float* bvec_s = (float*)(sm + OFF_BVEC);
    float* rel_s  = (float*)(sm + OFF_REL);
    float* mask_s = (float*)(sm + OFF_MASK);
    unsigned char* ridx_s = (unsigned char*)(sm + OFF_RIDX);

    const int t = threadIdx.x, wid = t >> 5, lane = t & 31;
    const int g = lane >> 2, tq = lane & 3;
    const int b = blockIdx.x;

    // ---- phase 0: zero v-frags (0 x garbage protection), stage tables + x frags ----
    {
        uint4 z = make_uint4(0, 0, 0, 0);
        uint4* v4 = (uint4*)(sm + OFF_VFH);
        for (int i = t; i < 2048; i += THREADS) v4[i] = z;  // VFH + VFL (32KB)
    }
    for (int i = t; i < 384; i += THREADS) bvec_s[i] = bvec[i];
    for (int i = t; i < 676; i += THREADS) rel_s[i] = rel_table[i];
    {
        const float* mw = mask + (size_t)(b & (NWIN - 1)) * 2401;
        for (int i = t; i < 2401; i += THREADS) {
            mask_s[i] = mw[i];
            const int n = i / 49, m = i - n * 49;
            ridx_s[i] = (unsigned char)((n / 7 - m / 7 + 6) * 13 + (n % 7 - m % 7 + 6));
        }
    }
    {
        const float4* xg = (const float4*)(x + (size_t)b * 6272);
        uint32_t* xh = (uint32_t*)(sm + OFF_XH);
        uint32_t* xl = (uint32_t*)(sm + OFF_XL);
        for (int i = t; i < 64 * 32; i += THREADS) {
            const int r = i >> 5, k0 = (i & 31) * 4;
            float4 v = make_float4(0.f, 0.f, 0.f, 0.f);
            if (r < N_TOK) v = xg[r * 32 + (i & 31)];
            __nv_bfloat16 h0, l0, h1, l1, h2, l2, h3, l3;
            split_bf16(v.x, h0, l0); split_bf16(v.y, h1, l1);
            split_bf16(v.z, h2, l2); split_bf16(v.w, h3, l3);
            const uint32_t ph01 = (uint32_t)__bfloat16_as_ushort(h0) | ((uint32_t)__bfloat16_as_ushort(h1) << 16);
            const uint32_t ph23 = (uint32_t)__bfloat16_as_ushort(h2) | ((uint32_t)__bfloat16_as_ushort(h3) << 16);
            const uint32_t pl01 = (uint32_t)__bfloat16_as_ushort(l0) | ((uint32_t)__bfloat16_as_ushort(l1) << 16);
            const uint32_t pl23 = (uint32_t)__bfloat16_as_ushort(l2) | ((uint32_t)__bfloat16_as_ushort(l3) << 16);
            const int mt = r >> 4, r16 = r & 15, g8 = r16 & 7;
            const int kc = k0 >> 4, kk = k0 & 15;
            const int reg = (r16 >= 8 ? 1 : 0) + (kk >= 8 ? 2 : 0);
            const int jj = (kk & 7) >> 1;
            const int base = (((mt * 8 + kc) * 32) + g8 * 4 + jj) * 4 + reg;
            xh[base] = ph01; xh[base + 4] = ph23;
            xl[base] = pl01; xl[base + 4] = pl23;
        }
    }
    __syncthreads();

    // ---- phase 1: projection, one 64x24 warp tile per warp ----
    {
        float c[4][3][4];
        #pragma unroll
        for (int mt = 0; mt < 4; mt++)
            #pragma unroll
            for (int j = 0; j < 3; j++)
                #pragma unroll
                for (int e = 0; e < 4; e++) c[mt][j][e] = 0.f;

        const uint2* wfh = (const uint2*)g_wfh;
        const uint2* wfl = (const uint2*)g_wfl;
        #pragma unroll
        for (int kc = 0; kc < 8; kc++) {
            uint4 ah[4], al[4];
            #pragma unroll
            for (int mt = 0; mt < 4; mt++) {
                const int idx = (((mt * 8 + kc) * 32) + lane) << 4;
                ah[mt] = *(const uint4*)(sm + OFF_XH + idx);
                al[mt] = *(const uint4*)(sm + OFF_XL + idx);
            }
            uint2 bh[3], bl[3];
            #pragma unroll
            for (int j = 0; j < 3; j++) {
                const int idx = ((wid * 3 + j) * 8 + kc) * 32 + lane;
                bh[j] = __ldg(&wfh[idx]);
                bl[j] = __ldg(&wfl[idx]);
            }
            #pragma unroll
            for (int mt = 0; mt < 4; mt++)
                #pragma unroll
                for (int j = 0; j < 3; j++) {
                    mma16816(c[mt][j], (const uint32_t*)&ah[mt], (const uint32_t*)&bh[j]);
                    mma16816(c[mt][j], (const uint32_t*)&ah[mt], (const uint32_t*)&bl[j]);
                    mma16816(c[mt][j], (const uint32_t*)&al[mt], (const uint32_t*)&bh[j]);
                }
        }

        // epilogue: +bias, split hi/lo, store into q/k/v FRAGMENT layouts
        const float scale = 0.17677669529663687f;  // 1/sqrt(32), folded into q
        #pragma unroll
        for (int j = 0; j < 3; j++)
            #pragma unroll
            for (int e = 0; e < 4; e++) {
                const int o = wid * 24 + j * 8 + tq * 2 + (e & 1);
                const int h = o / 96, rem = o - 96 * h;
                const int d = rem / 3, which = rem - 3 * d;
                const float bo = bvec_s[o];
                #pragma unroll
                for (int mt = 0; mt < 4; mt++) {
                    const int n = mt * 16 + g + (e >= 2 ? 8 : 0);
                    if (n >= N_TOK) continue;
                    float val = c[mt][j][e] + bo;
                    if (which == 0) val *= scale;
                    __nv_bfloat16 hi, lo;
                    split_bf16(val, hi, lo);
                    int addr;
                    if (which == 0) {        // q A-frag
                        const int li = ((n & 7) << 2) | ((d & 7) >> 1);
                        const int reg = ((n & 15) >= 8 ? 1 : 0) + ((d & 15) >= 8 ? 2 : 0);
                        addr = ((((h * 4 + (n >> 4)) * 2 + (d >> 4)) * 32 + li) * 4 + reg) * 4 + (d & 1) * 2;
                        *(__nv_bfloat16*)(sm + OFF_QFH + addr) = hi;
                        *(__nv_bfloat16*)(sm + OFF_QFL + addr) = lo;
                    } else if (which == 1) { // k B-frag (K-dim = d)
                        const int li = ((n & 7) << 2) | ((d & 7) >> 1);
                        const int reg = ((d & 15) >= 8 ? 1 : 0);
                        addr = ((((h * 7 + (n >> 3)) * 2 + (d >> 4)) * 32 + li) * 2 + reg) * 4 + (d & 1) * 2;
                        *(__nv_bfloat16*)(sm + OFF_KFH + addr) = hi;
                        *(__nv_bfloat16*)(sm + OFF_KFL + addr) = lo;
                    } else {                 // v B-frag (K-dim = key n, N-dim = d)
                        const int li = ((d & 7) << 2) | ((n & 7) >> 1);
                        const int reg = ((n & 15) >= 8 ? 1 : 0);
                        addr = ((((h * 4 + (n >> 4)) * 4 + (d >> 3)) * 32 + li) * 2 + reg) * 4 + (n & 1) * 2;
                        *(__nv_bfloat16*)(sm + OFF_VFH + addr) = hi;
                        *(__nv_bfloat16*)(sm + OFF_VFL + addr) = lo;
                    }
                }
            }
    }
    __syncthreads();

    // ---- phase 2: attention, one (head, 16-row tile) per warp ----
    {
        const int h = wid >> 2, mt = wid & 3;
        const int r0 = mt * 16 + g, r1 = r0 + 8;

        // q A-frags
        uint4 ah[2], al[2];
        #pragma unroll
        for (int kc = 0; kc < 2; kc++) {
            const int idx = (((h * 4 + mt) * 2 + kc) * 32 + lane) << 4;
            ah[kc] = *(const uint4*)(sm + OFF_QFH + idx);
            al[kc] = *(const uint4*)(sm + OFF_QFL + idx);
        }

        // S = q k^T  (7 n-tiles of 8 keys)
        float c[7][4];
        #pragma unroll
        for (int nt = 0; nt < 7; nt++)
            #pragma unroll
            for (int e = 0; e < 4; e++) c[nt][e] = 0.f;

        #pragma unroll
        for (int nt = 0; nt < 7; nt++)
            #pragma unroll
            for (int kc = 0; kc < 2; kc++) {
                const int idx = (((h * 7 + nt) * 2 + kc) * 32 + lane) << 3;
                const uint2 bh = *(const uint2*)(sm + OFF_KFH + idx);
                const uint2 bl = *(const uint2*)(sm + OFF_KFL + idx);
                mma16816(c[nt], (const uint32_t*)&ah[kc], (const uint32_t*)&bh);
                mma16816(c[nt], (const uint32_t*)&ah[kc], (const uint32_t*)&bl);
                mma16816(c[nt], (const uint32_t*)&al[kc], (const uint32_t*)&bh);
            }

        // bias + mask in c-frag layout
        #pragma unroll
        for (int nt = 0; nt < 7; nt++)
            #pragma unroll
            for (int e = 0; e < 4; e++) {
                const int r = (e >= 2) ? r1 : r0;
                const int m = nt * 8 + tq * 2 + (e & 1);
                if (m < N_TOK && r < N_TOK)
                    c[nt][e] += rel_s[(int)ridx_s[r * 49 + m] * NHEADS + h] + mask_s[r * 49 + m];
                else
                    c[nt][e] = -1e30f;
            }

        // softmax: rows r0 (e=0,1) and r1 (e=2,3); reduce across 4-lane group
        float mx0 = -1e30f, mx1 = -1e30f;
        #pragma unroll
        for (int nt = 0; nt < 7; nt++) {
            mx0 = fmaxf(mx0, fmaxf(c[nt][0], c[nt][1]));
            mx1 = fmaxf(mx1, fmaxf(c[nt][2], c[nt][3]));
        }
        mx0 = fmaxf(mx0, __shfl_xor_sync(~0u, mx0, 1));
        mx0 = fmaxf(mx0, __shfl_xor_sync(~0u, mx0, 2));
        mx1 = fmaxf(mx1, __shfl_xor_sync(~0u, mx1, 1));
        mx1 = fmaxf(mx1, __shfl_xor_sync(~0u, mx1, 2));
        float s0 = 0.f, s1 = 0.f;
        #pragma unroll
        for (int nt = 0; nt < 7; nt++) {
            c[nt][0] = __expf(c[nt][0] - mx0); s0 += c[nt][0];
            c[nt][1] = __expf(c[nt][1] - mx0); s0 += c[nt][1];
            c[nt][2] = __expf(c[nt][2] - mx1); s1 += c[nt][2];
            c[nt][3] = __expf(c[nt][3] - mx1); s1 += c[nt][3];
        }
        s0 += __shfl_xor_sync(~0u, s0, 1);
        s0 += __shfl_xor_sync(~0u, s0, 2);
        s1 += __shfl_xor_sync(~0u, s1, 1);
        s1 += __shfl_xor_sync(~0u, s1, 2);
        const float inv0 = 1.f / s0, inv1 = 1.f / s1;
        #pragma unroll
        for (int nt = 0; nt < 7; nt++) {
            c[nt][0] *= inv0; c[nt][1] *= inv0;
            c[nt][2] *= inv1; c[nt][3] *= inv1;
        }

        // PV: P (c-frags -> A-frags in registers) x V (B-frags)
        float o_[4][4];
        #pragma unroll
        for (int nd = 0; nd < 4; nd++)
            #pragma unroll
            for (int e = 0; e < 4; e++) o_[nd][e] = 0.f;

        #pragma unroll
        for (int kck = 0; kck < 4; kck++) {
            uint32_t pah[4], pal[4];
            pack_hl(c[2 * kck][0],     c[2 * kck][1],     pah[0], pal[0]);
            pack_hl(c[2 * kck][2],     c[2 * kck][3],     pah[1], pal[1]);
            pack_hl(c[2 * kck + 1][0], c[2 * kck + 1][1], pah[2], pal[2]);
            pack_hl(c[2 * kck + 1][2], c[2 * kck + 1][3], pah[3], pal[3]);
            #pragma unroll
            for (int nd = 0; nd < 4; nd++) {
                const int idx = (((h * 4 + kck) * 4 + nd) * 32 + lane) << 3;
                const uint2 vh = *(const uint2*)(sm + OFF_VFH + idx);
                const uint2 vl = *(const uint2*)(sm + OFF_VFL + idx);
                mma16816(o_[nd], pah, (const uint32_t*)&vh);
                mma16816(o_[nd], pah, (const uint32_t*)&vl);
                mma16816(o_[nd], pal, (const uint32_t*)&vh);
            }
        }

        // writeback
        float* ob = out + (size_t)b * 6272 + h * 32;
        #pragma unroll
        for (int nd = 0; nd < 4; nd++) {
            const int d0 = nd * 8 + tq * 2;
            if (r0 < N_TOK)
                *(float2*)(ob + r0 * 128 + d0) = make_float2(o_[nd][0], o_[nd][1]);
            if (r1 < N_TOK)
                *(float2*)(ob + r1 * 128 + d0) = make_float2(o_[nd][2], o_[nd][3]);
        }
    }
}

extern "C" void kernel_launch(void* const* d_in, const int* in_sizes, int n_in,
                              void* d_out, int out_size)
{
    const float* x    = (const float*)d_in[0];
    const float* mask = (const float*)d_in[1];
    const float* W    = (const float*)d_in[2];
    const float* bvec = (const float*)d_in[3];
    const float* rel  = (const float*)d_in[4];
    float* out = (float*)d_out;

    prep_w<<<96, 256>>>(W);
    cudaFuncSetAttribute(win_attn_kernel,
                         cudaFuncAttributeMaxDynamicSharedMemorySize, SMEM_TOTAL);
    win_attn_kernel<<<4096, THREADS, SMEM_TOTAL>>>(x, mask, bvec, rel, out);
}